// round 3
// baseline (speedup 1.0000x reference)
#include <cuda_runtime.h>
#include <cuda_fp16.h>

#define NN 262144
#define EE 4194304
#define GG 1024

// ---------------- scratch (device globals; no allocation allowed) ----------
__device__ __align__(16) int        g_count[NN];
__device__ __align__(16) int        g_off  [NN];     // exclusive bucket start
__device__ __align__(16) int        g_cur  [NN];     // cursor; == bucket end after build
__device__ __align__(16) int        g_bsum [256];
__device__ __align__(16) long long  g_ebuf [EE];     // packed (w_bits<<32)|src
__device__ __align__(16) float      g_dinv [NN];
__device__ __align__(16) float      g_y    [NN * 4]; // x * dinv (padded 3->4)
__device__ __align__(16) __half     g_zh   [NN * 16];// out1 * dinv  (fp16)
__device__ __align__(16) float      g_agg2 [NN * 16];// layer-2 neighbor aggregate
__device__ __align__(16) float      g_pool [GG * 16];
__device__ __align__(16) float      g_cnt  [GG];

__device__ __forceinline__ float leaky(float x) { return x > 0.0f ? x : 0.01f * x; }

__device__ __forceinline__ void red_add_v4(float* p, float a, float b, float c, float d) {
    asm volatile("red.global.add.v4.f32 [%0], {%1,%2,%3,%4};"
                 :: "l"(p), "f"(a), "f"(b), "f"(c), "f"(d) : "memory");
}

// ---------------- K0: zero count + pool ------------------------------------
__global__ void k_zero() {
    int i = blockIdx.x * blockDim.x + threadIdx.x;   // NN threads
    g_count[i] = 0;
    if (i < GG * 16) g_pool[i] = 0.0f;
    if (i < GG)      g_cnt[i]  = 0.0f;
}

// ---------------- K1: per-dst edge counts ----------------------------------
__global__ void k_count(const int* __restrict__ dst) {
    int e = blockIdx.x * blockDim.x + threadIdx.x;
    if (e < EE) atomicAdd(&g_count[dst[e]], 1);
}

// ---------------- K2a/b/c: exclusive prefix scan of counts -----------------
__global__ void k_scanA() {   // 256 blocks x 1024 threads
    __shared__ int sh[1024];
    int t = threadIdx.x;
    int i = blockIdx.x * 1024 + t;
    int v = g_count[i];
    sh[t] = v; __syncthreads();
    #pragma unroll
    for (int o = 1; o < 1024; o <<= 1) {
        int u = (t >= o) ? sh[t - o] : 0;
        __syncthreads();
        sh[t] += u;
        __syncthreads();
    }
    g_off[i] = sh[t] - v;                 // partial exclusive scan
    if (t == 1023) g_bsum[blockIdx.x] = sh[t];
}

__global__ void k_scanB() {   // 1 block x 256 threads
    __shared__ int sh[256];
    int t = threadIdx.x;
    int v = g_bsum[t];
    sh[t] = v; __syncthreads();
    #pragma unroll
    for (int o = 1; o < 256; o <<= 1) {
        int u = (t >= o) ? sh[t - o] : 0;
        __syncthreads();
        sh[t] += u;
        __syncthreads();
    }
    g_bsum[t] = sh[t] - v;                // exclusive
}

__global__ void k_scanC() {   // 256 blocks x 1024 threads
    int i = blockIdx.x * 1024 + threadIdx.x;
    int v = g_off[i] + g_bsum[blockIdx.x];
    g_off[i] = v;
    g_cur[i] = v;
}

// ---------------- K3: bucket edges by dst ----------------------------------
__global__ void k_build(const int* __restrict__ src, const int* __restrict__ dst,
                        const float* __restrict__ ew) {
    int e = blockIdx.x * blockDim.x + threadIdx.x;
    if (e >= EE) return;
    int d = dst[e];
    int pos = atomicAdd(&g_cur[d], 1);
    long long pk = ((long long)__float_as_int(ew[e]) << 32) | (unsigned int)src[e];
    g_ebuf[pos] = pk;
}

// ---------------- K4: warp/node: weighted degree -> dinv, y = x*dinv -------
__global__ void k_prep(const float* __restrict__ X) {
    int i = (blockIdx.x * blockDim.x + threadIdx.x) >> 5;
    int l = threadIdx.x & 31;
    if (i >= NN) return;
    int st = g_off[i], en = g_cur[i];
    float wsum = 0.0f;
    for (int e = st + l; e < en; e += 32) {
        long long pk = g_ebuf[e];
        wsum += __int_as_float((int)(pk >> 32));
    }
    #pragma unroll
    for (int o = 16; o; o >>= 1) wsum += __shfl_xor_sync(~0u, wsum, o);
    float di = rsqrtf(wsum + 1.0f);       // +1 self-loop
    if (l == 0) g_dinv[i] = di;
    if (l < 3)       g_y[i * 4 + l] = X[i * 3 + l] * di;
    else if (l == 3) g_y[i * 4 + 3] = 0.0f;
}

// ---------------- K5: warp/node layer 1: gather y, GEMM, act, store z fp16 -
__global__ void k_l1f(const float* __restrict__ W1, const float* __restrict__ b1) {
    int i = (blockIdx.x * blockDim.x + threadIdx.x) >> 5;
    int l = threadIdx.x & 31;
    if (i >= NN) return;
    int st = g_off[i], en = g_cur[i];
    float a0 = 0.f, a1 = 0.f, a2 = 0.f;
    for (int e = st + l; e < en; e += 32) {
        long long pk = g_ebuf[e];
        int   s  = (int)(pk & 0xffffffff);
        float wt = __int_as_float((int)(pk >> 32));
        float4 ys = *(const float4*)(g_y + s * 4);
        a0 += wt * ys.x; a1 += wt * ys.y; a2 += wt * ys.z;
    }
    #pragma unroll
    for (int o = 16; o; o >>= 1) {
        a0 += __shfl_xor_sync(~0u, a0, o);
        a1 += __shfl_xor_sync(~0u, a1, o);
        a2 += __shfl_xor_sync(~0u, a2, o);
    }
    float di = g_dinv[i];
    a0 = di * (a0 + g_y[i * 4 + 0]);      // broadcast loads (same addr all lanes)
    a1 = di * (a1 + g_y[i * 4 + 1]);
    a2 = di * (a2 + g_y[i * 4 + 2]);
    if (l < 16) {
        float v = __ldg(b1 + l) + a0 * __ldg(W1 + l)
                + a1 * __ldg(W1 + 16 + l) + a2 * __ldg(W1 + 32 + l);
        float z  = leaky(v) * di;          // z = out1 * dinv
        float zn = __shfl_down_sync(0xffffu, z, 1);
        if ((l & 1) == 0)
            ((__half2*)g_zh)[i * 8 + (l >> 1)] = __floats2half2_rn(z, zn);
    }
}

// ---------------- K6: warp/node layer 2 aggregate (8 edges x 4 quarters) ---
__global__ void k_l2agg() {
    int i = (blockIdx.x * blockDim.x + threadIdx.x) >> 5;
    int l = threadIdx.x & 31;
    if (i >= NN) return;
    int q = l & 3, grp = l >> 2;
    int st = g_off[i], en = g_cur[i];
    float4 acc = make_float4(0.f, 0.f, 0.f, 0.f);
    for (int e = st + grp; e < en; e += 8) {
        long long pk = g_ebuf[e];          // 4 lanes same addr -> broadcast
        int   s  = (int)(pk & 0xffffffff);
        float wt = __int_as_float((int)(pk >> 32));
        uint2 u = *(const uint2*)(g_zh + s * 16 + q * 4);   // 4 halves, coalesced 32B/group
        float2 f01 = __half22float2(*(const __half2*)&u.x);
        float2 f23 = __half22float2(*(const __half2*)&u.y);
        acc.x += wt * f01.x; acc.y += wt * f01.y;
        acc.z += wt * f23.x; acc.w += wt * f23.y;
    }
    #pragma unroll
    for (int o = 4; o < 32; o <<= 1) {     // reduce over edge-groups, keep q
        acc.x += __shfl_xor_sync(~0u, acc.x, o);
        acc.y += __shfl_xor_sync(~0u, acc.y, o);
        acc.z += __shfl_xor_sync(~0u, acc.z, o);
        acc.w += __shfl_xor_sync(~0u, acc.w, o);
    }
    if (l < 4) ((float4*)g_agg2)[i * 4 + q] = acc;   // lanes 0..3 hold q=0..3
}

// ---------------- K7: out2 + mean-pool scatter -----------------------------
__global__ void k_out2pool(const float* __restrict__ W2, const float* __restrict__ b2,
                           const int* __restrict__ batch) {
    __shared__ float sW[256], sb[16];
    int tid = threadIdx.x;
    if (tid < 256) sW[tid] = W2[tid];
    if (tid < 16)  sb[tid] = b2[tid];
    __syncthreads();

    int i = blockIdx.x * blockDim.x + tid;
    if (i >= NN) return;
    float di = g_dinv[i];

    float a[16];
    const float4* pA = (const float4*)(g_agg2 + i * 16);
    const uint4*  pZ = (const uint4*)(g_zh + i * 16);   // 16 halves = 2 x uint4
    #pragma unroll
    for (int h = 0; h < 2; h++) {
        uint4 zu = pZ[h];
        float2 z0 = __half22float2(*(const __half2*)&zu.x);
        float2 z1 = __half22float2(*(const __half2*)&zu.y);
        float2 z2 = __half22float2(*(const __half2*)&zu.z);
        float2 z3 = __half22float2(*(const __half2*)&zu.w);
        float zz[8] = {z0.x, z0.y, z1.x, z1.y, z2.x, z2.y, z3.x, z3.y};
        float4 va0 = pA[h * 2 + 0], va1 = pA[h * 2 + 1];
        float vv[8] = {va0.x, va0.y, va0.z, va0.w, va1.x, va1.y, va1.z, va1.w};
        #pragma unroll
        for (int k = 0; k < 8; k++) a[h * 8 + k] = di * (vv[k] + zz[k]);
    }
    float o[16];
    #pragma unroll
    for (int f = 0; f < 16; f++) {
        float v = sb[f];
        #pragma unroll
        for (int k = 0; k < 16; k++) v += a[k] * sW[k * 16 + f];
        o[f] = leaky(v);
    }
    int b = batch[i];
    float* pp = g_pool + b * 16;
    red_add_v4(pp +  0, o[0],  o[1],  o[2],  o[3]);
    red_add_v4(pp +  4, o[4],  o[5],  o[6],  o[7]);
    red_add_v4(pp +  8, o[8],  o[9],  o[10], o[11]);
    red_add_v4(pp + 12, o[12], o[13], o[14], o[15]);
    atomicAdd(&g_cnt[b], 1.0f);
}

// ---------------- K8: per-graph MLP heads ----------------------------------
__device__ __forceinline__ void layer16x16(const float* in, float* out,
                                           const float* W, const float* b, bool act) {
    #pragma unroll
    for (int f = 0; f < 16; f++) {
        float v = __ldg(b + f);
        #pragma unroll
        for (int k = 0; k < 16; k++) v += in[k] * __ldg(W + k * 16 + f);
        out[f] = act ? leaky(v) : v;
    }
}

__global__ void k_head(const float* __restrict__ Wp1, const float* __restrict__ bp1,
                       const float* __restrict__ Wp2, const float* __restrict__ bp2,
                       const float* __restrict__ Wp3, const float* __restrict__ bp3,
                       const float* __restrict__ Wt1, const float* __restrict__ bt1,
                       const float* __restrict__ Wt2, const float* __restrict__ bt2,
                       const float* __restrict__ Wt3, const float* __restrict__ bt3,
                       float* __restrict__ out) {
    int g = blockIdx.x * blockDim.x + threadIdx.x;
    if (g >= GG) return;
    float inv = 1.0f / fmaxf(g_cnt[g], 1.0f);
    float p[16], t1[16], t2[16];
    #pragma unroll
    for (int f = 0; f < 16; f++) p[f] = g_pool[g * 16 + f] * inv;

    layer16x16(p,  t1, Wp1, bp1, true);
    layer16x16(t1, t2, Wp2, bp2, true);
    float phi0 = __ldg(bp3 + 0), phi1 = __ldg(bp3 + 1);
    #pragma unroll
    for (int k = 0; k < 16; k++) {
        phi0 += t2[k] * __ldg(Wp3 + k * 2 + 0);
        phi1 += t2[k] * __ldg(Wp3 + k * 2 + 1);
    }
    layer16x16(p,  t1, Wt1, bt1, true);
    layer16x16(t1, t2, Wt2, bt2, true);
    float th0 = __ldg(bt3 + 0), th1 = __ldg(bt3 + 1);
    #pragma unroll
    for (int k = 0; k < 16; k++) {
        th0 += t2[k] * __ldg(Wt3 + k * 2 + 0);
        th1 += t2[k] * __ldg(Wt3 + k * 2 + 1);
    }
    out[g * 4 + 0] = phi0;
    out[g * 4 + 1] = phi1;
    out[g * 4 + 2] = th0;
    out[g * 4 + 3] = th1;
}

// ---------------- launch ----------------------------------------------------
extern "C" void kernel_launch(void* const* d_in, const int* in_sizes, int n_in,
                              void* d_out, int out_size) {
    const float* X  = (const float*)d_in[0];
    const int*   EI = (const int*)  d_in[1];
    const float* EW = (const float*)d_in[2];
    const int*   B  = (const int*)  d_in[3];
    int base = n_in - 16;
    const float* W1  = (const float*)d_in[base +  0];
    const float* b1  = (const float*)d_in[base +  1];
    const float* W2  = (const float*)d_in[base +  2];
    const float* b2  = (const float*)d_in[base +  3];
    const float* Wp1 = (const float*)d_in[base +  4];
    const float* bp1 = (const float*)d_in[base +  5];
    const float* Wp2 = (const float*)d_in[base +  6];
    const float* bp2 = (const float*)d_in[base +  7];
    const float* Wp3 = (const float*)d_in[base +  8];
    const float* bp3 = (const float*)d_in[base +  9];
    const float* Wt1 = (const float*)d_in[base + 10];
    const float* bt1 = (const float*)d_in[base + 11];
    const float* Wt2 = (const float*)d_in[base + 12];
    const float* bt2 = (const float*)d_in[base + 13];
    const float* Wt3 = (const float*)d_in[base + 14];
    const float* bt3 = (const float*)d_in[base + 15];

    const int* src = EI;
    const int* dst = EI + EE;

    k_zero     <<<NN / 256,        256>>>();
    k_count    <<<EE / 256,        256>>>(dst);
    k_scanA    <<<256,            1024>>>();
    k_scanB    <<<1,               256>>>();
    k_scanC    <<<256,            1024>>>();
    k_build    <<<EE / 256,        256>>>(src, dst, EW);
    k_prep     <<<(NN * 32) / 256, 256>>>(X);
    k_l1f      <<<(NN * 32) / 256, 256>>>(W1, b1);
    k_l2agg    <<<(NN * 32) / 256, 256>>>();
    k_out2pool <<<NN / 256,        256>>>(W2, b2, B);
    k_head     <<<GG / 128,        128>>>(Wp1, bp1, Wp2, bp2, Wp3, bp3,
                                          Wt1, bt1, Wt2, bt2, Wt3, bt3,
                                          (float*)d_out);
}

// round 4
// speedup vs baseline: 1.3057x; 1.3057x over previous
#include <cuda_runtime.h>
#include <cuda_fp16.h>

#define NN 262144
#define EE 4194304
#define GG 1024
#define CAP 4800   // smem edge-staging capacity per 256-node block (mean 4096, sd 64)

// ---------------- scratch (device globals; no allocation allowed) ----------
__device__ __align__(16)  int        g_count[NN];
__device__ __align__(16)  int        g_off  [NN];     // bucket start
__device__ __align__(16)  int        g_cur  [NN];     // cursor; == bucket end after build
__device__ __align__(16)  int        g_bsum [256];
__device__ __align__(16)  long long  g_ebuf [EE];     // packed (w_bits<<32)|src
__device__ __align__(16)  float      g_deg  [NN];     // weighted degree
__device__ __align__(16)  float      g_dinv [NN];
__device__ __align__(128) float      g_y    [NN * 4]; // x * dinv (padded 3->4)
__device__ __align__(128) __half     g_zh   [NN * 16];// out1 * dinv  (fp16, 32B/node)
__device__ __align__(16)  float      g_pool [GG * 16];
__device__ __align__(16)  float      g_cnt  [GG];

__device__ __forceinline__ float leaky(float x) { return x > 0.0f ? x : 0.01f * x; }

__device__ __forceinline__ void red_add_v4(float* p, float a, float b, float c, float d) {
    asm volatile("red.global.add.v4.f32 [%0], {%1,%2,%3,%4};"
                 :: "l"(p), "f"(a), "f"(b), "f"(c), "f"(d) : "memory");
}

__device__ __forceinline__ unsigned pack_h2(float a, float b) {
    __half2 h = __floats2half2_rn(a, b);
    return *(unsigned*)&h;
}

// ---------------- K0: zero scratch ------------------------------------------
__global__ void k_zero() {
    int i = blockIdx.x * blockDim.x + threadIdx.x;   // NN threads
    g_count[i] = 0;
    g_deg[i]   = 0.0f;
    if (i < GG * 16) g_pool[i] = 0.0f;
    if (i < GG)      g_cnt[i]  = 0.0f;
}

// ---------------- K1: per-dst edge counts -----------------------------------
__global__ void k_count(const int* __restrict__ dst) {
    int e = blockIdx.x * blockDim.x + threadIdx.x;
    if (e < EE) atomicAdd(&g_count[dst[e]], 1);
}

// ---------------- K2a/b/c: exclusive prefix scan (shfl-based) ---------------
__global__ void k_scanA() {   // 256 blocks x 1024 threads
    __shared__ int wsum[32];
    int t = threadIdx.x, lane = t & 31, warp = t >> 5;
    int i = blockIdx.x * 1024 + t;
    int v = g_count[i];
    int x = v;
    #pragma unroll
    for (int o = 1; o < 32; o <<= 1) {
        int u = __shfl_up_sync(~0u, x, o);
        if (lane >= o) x += u;
    }
    if (lane == 31) wsum[warp] = x;
    __syncthreads();
    if (warp == 0) {
        int w = wsum[lane];
        #pragma unroll
        for (int o = 1; o < 32; o <<= 1) {
            int u = __shfl_up_sync(~0u, w, o);
            if (lane >= o) w += u;
        }
        wsum[lane] = w;
    }
    __syncthreads();
    int base = (warp > 0) ? wsum[warp - 1] : 0;
    g_off[i] = base + x - v;              // block-local exclusive
    if (t == 1023) g_bsum[blockIdx.x] = wsum[31];
}

__global__ void k_scanB() {   // 1 block x 256 threads
    __shared__ int wsum[8];
    int t = threadIdx.x, lane = t & 31, warp = t >> 5;
    int v = g_bsum[t];
    int x = v;
    #pragma unroll
    for (int o = 1; o < 32; o <<= 1) {
        int u = __shfl_up_sync(~0u, x, o);
        if (lane >= o) x += u;
    }
    if (lane == 31) wsum[warp] = x;
    __syncthreads();
    if (warp == 0 && lane < 8) {
        int w = wsum[lane];
        #pragma unroll
        for (int o = 1; o < 8; o <<= 1) {
            int u = __shfl_up_sync(0xffu, w, o);
            if (lane >= o) w += u;
        }
        wsum[lane] = w;
    }
    __syncthreads();
    int base = (warp > 0) ? wsum[warp - 1] : 0;
    g_bsum[t] = base + x - v;             // exclusive
}

__global__ void k_scanC() {   // 256 blocks x 1024 threads
    int i = blockIdx.x * 1024 + threadIdx.x;
    int v = g_off[i] + g_bsum[blockIdx.x];
    g_off[i] = v;
    g_cur[i] = v;
}

// ---------------- K3: bucket edges by dst + weighted degree -----------------
__global__ void k_build(const int* __restrict__ src, const int* __restrict__ dst,
                        const float* __restrict__ ew) {
    int e = blockIdx.x * blockDim.x + threadIdx.x;
    if (e >= EE) return;
    int d = dst[e];
    float w = ew[e];
    int pos = atomicAdd(&g_cur[d], 1);
    long long pk = ((long long)__float_as_int(w) << 32) | (unsigned int)src[e];
    g_ebuf[pos] = pk;
    atomicAdd(&g_deg[d], w);
}

// ---------------- K4: elementwise dinv, y = x*dinv --------------------------
__global__ void k_prep(const float* __restrict__ X) {
    int i = blockIdx.x * blockDim.x + threadIdx.x;
    if (i >= NN) return;
    float di = rsqrtf(g_deg[i] + 1.0f);   // +1 self-loop
    g_dinv[i] = di;
    ((float4*)g_y)[i] = make_float4(X[i * 3 + 0] * di, X[i * 3 + 1] * di,
                                    X[i * 3 + 2] * di, 0.0f);
}

// ---------------- K5: layer 1 fused, smem-staged ebuf -----------------------
__global__ void k_l1f(const float* __restrict__ W1, const float* __restrict__ b1) {
    __shared__ long long se[CAP];
    __shared__ float sW[48], sb[16];
    int tid = threadIdx.x;
    int node0 = blockIdx.x * 256;
    if (tid < 48) sW[tid] = W1[tid];
    if (tid < 16) sb[tid] = b1[tid];

    int base = g_off[node0];
    int end  = g_cur[node0 + 255];
    int cnt  = end - base;
    bool fit = (cnt <= CAP);
    if (fit)
        for (int j = tid; j < cnt; j += 256) se[j] = g_ebuf[base + j];
    __syncthreads();

    int i  = node0 + tid;
    int st = g_off[i], en = g_cur[i];
    float a0 = 0.f, a1 = 0.f, a2 = 0.f;
    if (fit) {
        for (int e = st - base; e < en - base; e++) {
            long long pk = se[e];
            int   s  = (int)(pk & 0xffffffff);
            float wt = __int_as_float((int)(pk >> 32));
            float4 ys = ((const float4*)g_y)[s];
            a0 += wt * ys.x; a1 += wt * ys.y; a2 += wt * ys.z;
        }
    } else {
        for (int e = st; e < en; e++) {
            long long pk = g_ebuf[e];
            int   s  = (int)(pk & 0xffffffff);
            float wt = __int_as_float((int)(pk >> 32));
            float4 ys = ((const float4*)g_y)[s];
            a0 += wt * ys.x; a1 += wt * ys.y; a2 += wt * ys.z;
        }
    }
    float di = g_dinv[i];
    float4 yi = ((const float4*)g_y)[i];
    a0 = di * (a0 + yi.x);
    a1 = di * (a1 + yi.y);
    a2 = di * (a2 + yi.z);

    float o[16];
    #pragma unroll
    for (int f = 0; f < 16; f++) {
        float v = sb[f] + a0 * sW[f] + a1 * sW[16 + f] + a2 * sW[32 + f];
        o[f] = leaky(v) * di;                        // z = out1 * dinv
    }
    uint4* zp = (uint4*)(g_zh + i * 16);
    zp[0] = make_uint4(pack_h2(o[0],  o[1]),  pack_h2(o[2],  o[3]),
                       pack_h2(o[4],  o[5]),  pack_h2(o[6],  o[7]));
    zp[1] = make_uint4(pack_h2(o[8],  o[9]),  pack_h2(o[10], o[11]),
                       pack_h2(o[12], o[13]), pack_h2(o[14], o[15]));
}

// ---------------- K6: layer 2 + out2 + mean-pool, fused, smem-staged --------
__global__ void k_l2pool(const float* __restrict__ W2, const float* __restrict__ b2,
                         const int* __restrict__ batch) {
    __shared__ long long se[CAP];
    __shared__ float sW[256], sb[16];
    int tid = threadIdx.x;
    int node0 = blockIdx.x * 256;
    sW[tid] = W2[tid];
    if (tid < 16) sb[tid] = b2[tid];

    int base = g_off[node0];
    int end  = g_cur[node0 + 255];
    int cnt  = end - base;
    bool fit = (cnt <= CAP);
    if (fit)
        for (int j = tid; j < cnt; j += 256) se[j] = g_ebuf[base + j];
    __syncthreads();

    int i  = node0 + tid;
    int st = g_off[i], en = g_cur[i];
    float acc[16];
    #pragma unroll
    for (int k = 0; k < 16; k++) acc[k] = 0.0f;

    #pragma unroll 1
    for (int e = fit ? (st - base) : st; e < (fit ? (en - base) : en); e++) {
        long long pk = fit ? se[e] : g_ebuf[e];
        int   s  = (int)(pk & 0xffffffff);
        float wt = __int_as_float((int)(pk >> 32));
        const uint4* zp = (const uint4*)(g_zh + s * 16);
        uint4 u0 = zp[0], u1 = zp[1];
        unsigned uu[8] = {u0.x, u0.y, u0.z, u0.w, u1.x, u1.y, u1.z, u1.w};
        #pragma unroll
        for (int q = 0; q < 8; q++) {
            float2 f = __half22float2(*(const __half2*)&uu[q]);
            acc[q * 2 + 0] += wt * f.x;
            acc[q * 2 + 1] += wt * f.y;
        }
    }

    float di = g_dinv[i];
    float a[16];
    const uint4* zself = (const uint4*)(g_zh + i * 16);
    uint4 s0 = zself[0], s1 = zself[1];
    unsigned su[8] = {s0.x, s0.y, s0.z, s0.w, s1.x, s1.y, s1.z, s1.w};
    #pragma unroll
    for (int q = 0; q < 8; q++) {
        float2 f = __half22float2(*(const __half2*)&su[q]);
        a[q * 2 + 0] = di * (acc[q * 2 + 0] + f.x);
        a[q * 2 + 1] = di * (acc[q * 2 + 1] + f.y);
    }
    float o[16];
    #pragma unroll
    for (int f = 0; f < 16; f++) {
        float v = sb[f];
        #pragma unroll
        for (int k = 0; k < 16; k++) v += a[k] * sW[k * 16 + f];
        o[f] = leaky(v);
    }
    int b = batch[i];
    float* pp = g_pool + b * 16;
    red_add_v4(pp +  0, o[0],  o[1],  o[2],  o[3]);
    red_add_v4(pp +  4, o[4],  o[5],  o[6],  o[7]);
    red_add_v4(pp +  8, o[8],  o[9],  o[10], o[11]);
    red_add_v4(pp + 12, o[12], o[13], o[14], o[15]);
    atomicAdd(&g_cnt[b], 1.0f);
}

// ---------------- K7: per-graph MLP heads -----------------------------------
__device__ __forceinline__ void layer16x16(const float* in, float* out,
                                           const float* W, const float* b, bool act) {
    #pragma unroll
    for (int f = 0; f < 16; f++) {
        float v = __ldg(b + f);
        #pragma unroll
        for (int k = 0; k < 16; k++) v += in[k] * __ldg(W + k * 16 + f);
        out[f] = act ? leaky(v) : v;
    }
}

__global__ void k_head(const float* __restrict__ Wp1, const float* __restrict__ bp1,
                       const float* __restrict__ Wp2, const float* __restrict__ bp2,
                       const float* __restrict__ Wp3, const float* __restrict__ bp3,
                       const float* __restrict__ Wt1, const float* __restrict__ bt1,
                       const float* __restrict__ Wt2, const float* __restrict__ bt2,
                       const float* __restrict__ Wt3, const float* __restrict__ bt3,
                       float* __restrict__ out) {
    int g = blockIdx.x * blockDim.x + threadIdx.x;
    if (g >= GG) return;
    float inv = 1.0f / fmaxf(g_cnt[g], 1.0f);
    float p[16], t1[16], t2[16];
    #pragma unroll
    for (int f = 0; f < 16; f++) p[f] = g_pool[g * 16 + f] * inv;

    layer16x16(p,  t1, Wp1, bp1, true);
    layer16x16(t1, t2, Wp2, bp2, true);
    float phi0 = __ldg(bp3 + 0), phi1 = __ldg(bp3 + 1);
    #pragma unroll
    for (int k = 0; k < 16; k++) {
        phi0 += t2[k] * __ldg(Wp3 + k * 2 + 0);
        phi1 += t2[k] * __ldg(Wp3 + k * 2 + 1);
    }
    layer16x16(p,  t1, Wt1, bt1, true);
    layer16x16(t1, t2, Wt2, bt2, true);
    float th0 = __ldg(bt3 + 0), th1 = __ldg(bt3 + 1);
    #pragma unroll
    for (int k = 0; k < 16; k++) {
        th0 += t2[k] * __ldg(Wt3 + k * 2 + 0);
        th1 += t2[k] * __ldg(Wt3 + k * 2 + 1);
    }
    out[g * 4 + 0] = phi0;
    out[g * 4 + 1] = phi1;
    out[g * 4 + 2] = th0;
    out[g * 4 + 3] = th1;
}

// ---------------- launch -----------------------------------------------------
extern "C" void kernel_launch(void* const* d_in, const int* in_sizes, int n_in,
                              void* d_out, int out_size) {
    const float* X  = (const float*)d_in[0];
    const int*   EI = (const int*)  d_in[1];
    const float* EW = (const float*)d_in[2];
    const int*   B  = (const int*)  d_in[3];
    int base = n_in - 16;
    const float* W1  = (const float*)d_in[base +  0];
    const float* b1  = (const float*)d_in[base +  1];
    const float* W2  = (const float*)d_in[base +  2];
    const float* b2  = (const float*)d_in[base +  3];
    const float* Wp1 = (const float*)d_in[base +  4];
    const float* bp1 = (const float*)d_in[base +  5];
    const float* Wp2 = (const float*)d_in[base +  6];
    const float* bp2 = (const float*)d_in[base +  7];
    const float* Wp3 = (const float*)d_in[base +  8];
    const float* bp3 = (const float*)d_in[base +  9];
    const float* Wt1 = (const float*)d_in[base + 10];
    const float* bt1 = (const float*)d_in[base + 11];
    const float* Wt2 = (const float*)d_in[base + 12];
    const float* bt2 = (const float*)d_in[base + 13];
    const float* Wt3 = (const float*)d_in[base + 14];
    const float* bt3 = (const float*)d_in[base + 15];

    const int* src = EI;
    const int* dst = EI + EE;

    k_zero   <<<NN / 256, 256>>>();
    k_count  <<<EE / 256, 256>>>(dst);
    k_scanA  <<<256,     1024>>>();
    k_scanB  <<<1,        256>>>();
    k_scanC  <<<256,     1024>>>();
    k_build  <<<EE / 256, 256>>>(src, dst, EW);
    k_prep   <<<NN / 256, 256>>>(X);
    k_l1f    <<<NN / 256, 256>>>(W1, b1);
    k_l2pool <<<NN / 256, 256>>>(W2, b2, B);
    k_head   <<<GG / 128, 128>>>(Wp1, bp1, Wp2, bp2, Wp3, bp3,
                                 Wt1, bt1, Wt2, bt2, Wt3, bt3,
                                 (float*)d_out);
}